// round 12
// baseline (speedup 1.0000x reference)
#include <cuda_runtime.h>
#include <stdint.h>

// SymmetricRBM: B=65536 independent Gibbs chains, N=64 visible, ALPHA=4 hidden groups,
// circulant weights from kernel[4][64]. One warp per sample; binary states as u32-pair masks.
//
// Launch-constant tables in shared memory, PRE-SCALED by -log2(e) so accumulators
// directly produce the MUFU.EX2 argument for exp(-z):
//   Tt  [256][64]  float2 : wh pair-signature table
//   Twv4[16][256]  float4 : wv nibble table, rows quadruplicated (imm offsets)
// Final mean fused into the same kernel via last-block-out reduction (deterministic
// fixed-order sum; ticket reset each launch for graph replay).

#define NV      64
#define ALPHA   4
#define BATCH   65536
#define KSTEPS  10
#define TPB     1024
#define WPB     32             // warps (=samples) per block
#define NBLK    (BATCH / WPB)  // 2048 blocks

#define NEG_LOG2E (-1.4426950408889634f)
#define LN2F      (0.6931471805599453f)

// dynamic smem layout
#define T_BYTES    (256 * 64 * 8)            // float2 Tt[256][64]   = 131072
#define KT4_OFF    T_BYTES
#define KT4_BYTES  (64 * 16)                 // float4 kT4[64]       = 1024
#define W_OFF      (KT4_OFF + KT4_BYTES)
#define W_BYTES    (16 * 64 * 4)             // float  W[16][64]     = 4096
#define TWV_OFF    (W_OFF + W_BYTES)
#define TWV_BYTES  (16 * 256 * 16)           // float4 Twv4[16][256] = 65536
#define WSUM_OFF   (TWV_OFF + TWV_BYTES)
#define WSUM_BYTES (WPB * 8)
#define SMEM_BYTES (WSUM_OFF + WSUM_BYTES)   // 201984

struct GibbsKeys {
    uint32_t kh0[KSTEPS], kh1[KSTEPS];
    uint32_t kv0[KSTEPS], kv1[KSTEPS];
};

__device__ double g_partials[NBLK];
__device__ unsigned int g_done = 0;

// ---------------- packed f32x2 helpers ----------------

__device__ __forceinline__ void addf32x2(uint64_t& acc, uint64_t v) {
    asm("add.rn.f32x2 %0, %0, %1;" : "+l"(acc) : "l"(v));
}
__device__ __forceinline__ void unpack2(float& lo, float& hi, uint64_t v) {
    uint32_t a, b;
    asm("mov.b64 {%0, %1}, %2;" : "=r"(a), "=r"(b) : "l"(v));
    lo = __uint_as_float(a); hi = __uint_as_float(b);
}
__device__ __forceinline__ uint64_t packf2(float lo, float hi) {
    uint64_t r;
    asm("mov.b64 %0, {%1, %2};" : "=l"(r)
        : "r"(__float_as_uint(lo)), "r"(__float_as_uint(hi)));
    return r;
}
__device__ __forceinline__ float ex2f(float x) {
    float r;
    asm("ex2.approx.f32 %0, %1;" : "=f"(r) : "f"(x));
    return r;
}

// ---------------- Threefry-2x32 (20 rounds), JAX-compatible ----------------

__host__ static uint32_t rotl32h(uint32_t x, int r) {
    return (x << r) | (x >> (32 - r));
}

__host__ static void tf2x32_host(uint32_t k0, uint32_t k1, uint32_t c0, uint32_t c1,
                                 uint32_t* o0, uint32_t* o1) {
    uint32_t ks2 = k0 ^ k1 ^ 0x1BD11BDAu;
    uint32_t x0 = c0 + k0, x1 = c1 + k1;
#define HR4A x0+=x1; x1=rotl32h(x1,13); x1^=x0; x0+=x1; x1=rotl32h(x1,15); x1^=x0; \
             x0+=x1; x1=rotl32h(x1,26); x1^=x0; x0+=x1; x1=rotl32h(x1, 6); x1^=x0;
#define HR4B x0+=x1; x1=rotl32h(x1,17); x1^=x0; x0+=x1; x1=rotl32h(x1,29); x1^=x0; \
             x0+=x1; x1=rotl32h(x1,16); x1^=x0; x0+=x1; x1=rotl32h(x1,24); x1^=x0;
    HR4A; x0 += k1;  x1 += ks2 + 1u;
    HR4B; x0 += ks2; x1 += k0  + 2u;
    HR4A; x0 += k0;  x1 += k1  + 3u;
    HR4B; x0 += k1;  x1 += ks2 + 4u;
    HR4A; x0 += ks2; x1 += k0  + 5u;
    *o0 = x0; *o1 = x1;
}
#undef HR4A
#undef HR4B

__device__ __forceinline__ uint32_t rotl32d(uint32_t x, int r) {
    return __funnelshift_l(x, x, r);
}

// counter hi word always 0; x1 passed pre-added with k1 (x1 = ctr + k1).
// JAX partitionable random_bits -> x0 ^ x1.
__device__ __forceinline__ uint32_t tf_bits_x1(uint32_t k0, uint32_t k1, uint32_t ks2,
                                               uint32_t x1) {
    uint32_t x0 = k0;
#define R4A  x0+=x1; x1=rotl32d(x1,13); x1^=x0; x0+=x1; x1=rotl32d(x1,15); x1^=x0; \
             x0+=x1; x1=rotl32d(x1,26); x1^=x0; x0+=x1; x1=rotl32d(x1, 6); x1^=x0;
#define R4B  x0+=x1; x1=rotl32d(x1,17); x1^=x0; x0+=x1; x1=rotl32d(x1,29); x1^=x0; \
             x0+=x1; x1=rotl32d(x1,16); x1^=x0; x0+=x1; x1=rotl32d(x1,24); x1^=x0;
    R4A; x0 += k1;  x1 += ks2 + 1u;
    R4B; x0 += ks2; x1 += k0  + 2u;
    R4A; x0 += k0;  x1 += k1  + 3u;
    R4B; x0 += k1;  x1 += ks2 + 4u;
    R4A; x0 += ks2; x1 += k0  + 5u;
    return x0 ^ x1;
#undef R4A
#undef R4B
}

__device__ __forceinline__ float u01(uint32_t bits) {
    return __uint_as_float((bits >> 9) | 0x3f800000u) - 1.0f;
}

// ---------------- wv: circulant forward via quadruplicated nibble table ----------------
// Accumulators hold SCALED values wp = -log2e*(wv+cc).
struct WvAcc { uint64_t P0, P1, P2, P3; };

__device__ __forceinline__ WvAcc compute_wv(uint32_t lo, uint32_t hi, int lane,
                                            const unsigned char* __restrict__ TwvRaw,
                                            uint64_t CC01, uint64_t CC23) {
    // lane n (n<16) owns nibble n of (lo|hi<<32), pre-scaled to its 4096-byte row offset
    uint32_t nib = (((lane < 8) ? (lo >> (4 * lane)) : (hi >> ((4 * lane) & 31))) & 15u) << 12;

    WvAcc A; A.P0 = CC01; A.P1 = CC23; A.P2 = CC01; A.P3 = CC23;
    const unsigned char* pbase = TwvRaw + (uint32_t)(((-lane) & 63) << 4);
#pragma unroll
    for (int n = 0; n < 16; n++) {
        uint32_t rowoff = (uint32_t)__shfl_sync(0xffffffffu, (int)nib, n);
        const unsigned char* p = pbase + rowoff;
        ulonglong2 x = *(const ulonglong2*)(p + 64 * n);
        ulonglong2 y = *(const ulonglong2*)(p + 64 * n + 512);
        addf32x2(A.P0, x.x); addf32x2(A.P1, x.y);
        addf32x2(A.P2, y.x); addf32x2(A.P3, y.y);
    }
    return A;
}

__device__ __forceinline__ void unpack_wv(const WvAcc& A, float* w) {
    unpack2(w[0], w[2], A.P0);
    unpack2(w[4], w[6], A.P1);
    unpack2(w[1], w[3], A.P2);
    unpack2(w[5], w[7], A.P3);
}

// softplus sum from SCALED wp = -log2e*z:
//   softplus(z) = ln2*max(-wp,0) + log1p(2^(-|wp|)),  -|wp| = min(wp,-wp)
__device__ __forceinline__ float softplus_sum(const float* w) {
    float s = 0.0f;
#pragma unroll
    for (int q = 0; q < 8; q++) {
        float wp = w[q];
        float nw = -wp;
        float t  = ex2f(fminf(wp, nw));
        s += fmaf(fmaxf(nw, 0.0f), LN2F, log1pf(t));
    }
    return s;
}

// Bernoulli(sigmoid(z)) from scaled wp = -log2e*z: e = 2^wp; u < 1/(1+e) <=> u*e+u < 1
__device__ __forceinline__ int bern_sig(float u, float wp) {
    float e = ex2f(wp);
    return fmaf(u, e, u) < 1.0f;
}

// ---------------- main kernel: one warp per batch sample + fused reduction ----------------

__global__ void __launch_bounds__(TPB, 1)
rbm_kernel(const float* __restrict__ v_data, const float* __restrict__ kern,
           const float* __restrict__ bsc, const float* __restrict__ cvec,
           float* __restrict__ out, GibbsKeys keys) {
    extern __shared__ unsigned char smem_raw[];
    float2* Tt   = (float2*)smem_raw;                  // [256][64] pair (i, i+32), SCALED
    float4* kT4  = (float4*)(smem_raw + KT4_OFF);      // [64]
    float*  W    = (float*)(smem_raw + W_OFF);         // [16][64]
    float4* Twv4 = (float4*)(smem_raw + TWV_OFF);      // [16][256] quadruplicated, SCALED
    double* wsum = (double*)(smem_raw + WSUM_OFF);     // [WPB]
    const unsigned char* TwvRaw = smem_raw + TWV_OFF;
    const unsigned char* TtRaw  = smem_raw;
    __shared__ int s_last;

    const int tid = threadIdx.x;

    // ---- phase 1: W[s][d] = sum_a bit_a(s)*k[a][d] (unscaled) and kT4[d] ----
    {
        if (tid < 16 * 64) {
            int s = tid >> 6, d = tid & 63;
            float acc = 0.0f;
#pragma unroll
            for (int a = 0; a < ALPHA; a++)
                if ((s >> a) & 1) acc += kern[a * NV + d];
            W[tid] = acc;
        }
        if (tid < 64)
            kT4[tid] = make_float4(kern[tid], kern[NV + tid], kern[2 * NV + tid], kern[3 * NV + tid]);
    }
    __syncthreads();

    // ---- phase 2a: Tt[idx8][e] (wh pair table), scaled by -log2e ----
    for (int idx = tid; idx < 256 * 64; idx += TPB) {
        int i8 = idx >> 6, e = idx & 63;
        int slo = (i8 & 1) | ((i8 >> 1) & 2) | ((i8 >> 2) & 4) | ((i8 >> 3) & 8);
        int shi = ((i8 >> 1) & 1) | ((i8 >> 2) & 2) | ((i8 >> 3) & 4) | ((i8 >> 4) & 8);
        int em1 = (e - 1) & 63;
        float x = W[slo * 64 + e] + W[shi * 64 + em1];
        float y = W[slo * 64 + (e ^ 32)] + W[shi * 64 + (em1 ^ 32)];
        Tt[idx] = make_float2(NEG_LOG2E * x, NEG_LOG2E * y);
    }

    // ---- phase 2b: Twv4[s][i] = -log2e * sum_{r in bits(s)} kT4[((i&63)+r)&63] ----
    for (int idx = tid; idx < 16 * 256; idx += TPB) {
        int s = idx >> 8, d = idx & 63;
        float4 acc = make_float4(0.f, 0.f, 0.f, 0.f);
#pragma unroll
        for (int r = 0; r < 4; r++) {
            if ((s >> r) & 1) {
                float4 k = kT4[(d + r) & 63];
                acc.x += k.x; acc.y += k.y; acc.z += k.z; acc.w += k.w;
            }
        }
        Twv4[idx] = make_float4(NEG_LOG2E * acc.x, NEG_LOG2E * acc.y,
                                NEG_LOG2E * acc.z, NEG_LOG2E * acc.w);
    }
    __syncthreads();

    const int lane = tid & 31;
    const int wid  = tid >> 5;
    const int b    = blockIdx.x * WPB + wid;

    const float bS = __ldg(bsc);
    const float sc_bS = NEG_LOG2E * bS;
    const uint64_t CC01 = packf2(NEG_LOG2E * __ldg(cvec + 0), NEG_LOG2E * __ldg(cvec + 1));
    const uint64_t CC23 = packf2(NEG_LOG2E * __ldg(cvec + 2), NEG_LOG2E * __ldg(cvec + 3));
    const uint64_t BSS  = packf2(sc_bS, sc_bS);

    // pack visible data into warp-uniform masks
    const float va = v_data[b * NV + lane];
    const float vb = v_data[b * NV + 32 + lane];
    uint32_t vlo = __ballot_sync(0xffffffffu, va > 0.5f);
    uint32_t vhi = __ballot_sync(0xffffffffu, vb > 0.5f);
    const uint32_t dlo = vlo, dhi = vhi;

    float w[8];

    // scaled wv(V_data)+cc: shared by sp_d and step 0's hidden sampling
    {
        WvAcc A = compute_wv(dlo, dhi, lane, TwvRaw, CC01, CC23);
        unpack_wv(A, w);
    }
    const float sp_d = softplus_sum(w);

    const uint32_t bb = (uint32_t)b * (ALPHA * NV) + (uint32_t)lane;  // hidden ctr base
    const uint32_t mv = (uint32_t)b * NV + (uint32_t)lane;            // visible ctr base
    const uint32_t ebOff0 = (uint32_t)(((lane - 1) & 63) << 3);       // byte offset of e within Tt row
    const int shsig = (2 * lane) & 31;                                // per-lane wh signature shift

#pragma unroll 1
    for (int t = 0; t < KSTEPS; t++) {
        // ---- sample hidden from scaled w ----
        const uint32_t kh0 = keys.kh0[t], kh1 = keys.kh1[t];
        const uint32_t khs2 = kh0 ^ kh1 ^ 0x1BD11BDAu;
        const uint32_t bbk  = bb + kh1;  // counter base pre-added with k1
        uint32_t hlo[ALPHA], hhi[ALPHA];
#pragma unroll
        for (int a = 0; a < ALPHA; a++) {
            float u0 = u01(tf_bits_x1(kh0, kh1, khs2, bbk + (uint32_t)(a * NV)));
            float u1 = u01(tf_bits_x1(kh0, kh1, khs2, bbk + (uint32_t)(a * NV + 32)));
            int h0 = bern_sig(u0, w[a * 2 + 0]);
            int h1 = bern_sig(u1, w[a * 2 + 1]);
            hlo[a] = __ballot_sync(0xffffffffu, h0);
            hhi[a] = __ballot_sync(0xffffffffu, h1);
        }

        // ---- per-lane wh signature (IMAD combine), pre-scaled to 512B row ----
        uint32_t s0, s1, s2, s3;
        if (lane < 16) {
            s0 = hlo[0] >> shsig; s1 = hlo[1] >> shsig;
            s2 = hlo[2] >> shsig; s3 = hlo[3] >> shsig;
        } else {
            s0 = hhi[0] >> shsig; s1 = hhi[1] >> shsig;
            s2 = hhi[2] >> shsig; s3 = hhi[3] >> shsig;
        }
        uint32_t sigOff = ((s0 & 3u) + (s1 & 3u) * 4u + (s2 & 3u) * 16u + (s3 & 3u) * 64u) * 512u;

        // ---- wh: 32 dense iterations, SHFL-broadcast row offset, dual packed accums ----
        uint64_t WHa = BSS, WHb = 0ull;  // scaled: -log2e*(wh+bS) when merged
#pragma unroll
        for (int mm = 0; mm < 32; mm += 2) {
            uint32_t ro0 = (uint32_t)__shfl_sync(0xffffffffu, (int)sigOff, mm);
            uint32_t e0  = (ebOff0 - 16u * (uint32_t)mm) & 511u;
            addf32x2(WHa, *(const uint64_t*)(TtRaw + ro0 + e0));
            uint32_t ro1 = (uint32_t)__shfl_sync(0xffffffffu, (int)sigOff, mm + 1);
            uint32_t e1  = (ebOff0 - 16u * (uint32_t)(mm + 1)) & 511u;
            addf32x2(WHb, *(const uint64_t*)(TtRaw + ro1 + e1));
        }
        addf32x2(WHa, WHb);
        float wh0, wh1;
        unpack2(wh0, wh1, WHa);

        // ---- sample visible ----
        const uint32_t kv0 = keys.kv0[t], kv1 = keys.kv1[t];
        const uint32_t kvs2 = kv0 ^ kv1 ^ 0x1BD11BDAu;
        const uint32_t mvk  = mv + kv1;
        float u0 = u01(tf_bits_x1(kv0, kv1, kvs2, mvk));
        float u1 = u01(tf_bits_x1(kv0, kv1, kvs2, mvk + 32u));
        int n0 = bern_sig(u0, wh0);
        int n1 = bern_sig(u1, wh1);
        vlo = __ballot_sync(0xffffffffu, n0);
        vhi = __ballot_sync(0xffffffffu, n1);

        // ---- scaled wv of new V (next step's hidden sampling, or sp_m after t=9) ----
        WvAcc A = compute_wv(vlo, vhi, lane, TwvRaw, CC01, CC23);
        unpack_wv(A, w);
    }

    const float sp_m = softplus_sum(w);

    // fe_data - fe_model = bS*(S_m - S_d) + (SP_m - SP_d)
    float x = sp_m - sp_d;
#pragma unroll
    for (int off = 16; off; off >>= 1) x += __shfl_xor_sync(0xffffffffu, x, off);

    if (lane == 0) {
        x += bS * (float)((__popc(vlo) + __popc(vhi)) - (__popc(dlo) + __popc(dhi)));
        wsum[wid] = (double)x;
    }
    __syncthreads();
    if (tid == 0) {
        double s = 0.0;
#pragma unroll
        for (int i = 0; i < WPB; i++) s += wsum[i];
        g_partials[blockIdx.x] = s;
        // last-block ticket (release partial first)
        __threadfence();
        unsigned int old = atomicAdd(&g_done, 1u);
        s_last = (old == (unsigned int)(NBLK - 1));
    }
    __syncthreads();

    // ---- last block: deterministic fixed-order reduction over g_partials ----
    if (s_last) {
        __threadfence();  // acquire: partials from all blocks visible
        double* red = (double*)smem_raw;  // reuse table space (tables dead now)
        double s = 0.0;
#pragma unroll
        for (int i = tid; i < NBLK; i += TPB) s += g_partials[i];  // fixed order
        red[tid] = s;
        __syncthreads();
        for (int off = TPB / 2; off; off >>= 1) {
            if (tid < off) red[tid] += red[tid + off];
            __syncthreads();
        }
        if (tid == 0) {
            out[0] = (float)(red[0] / (double)BATCH);
            g_done = 0;  // reset ticket for next graph replay
        }
    }
}

// ---------------- launch ----------------

extern "C" void kernel_launch(void* const* d_in, const int* in_sizes, int n_in,
                              void* d_out, int out_size) {
    (void)in_sizes; (void)n_in; (void)out_size;
    const float* v_data = (const float*)d_in[0];
    const float* kern   = (const float*)d_in[1];
    const float* bsc    = (const float*)d_in[2];
    const float* cvec   = (const float*)d_in[3];

    // JAX key schedule: key(42)=(0,42); fold-like split: keys[i]=threefry(k,(0,i))
    GibbsKeys keys;
    uint32_t k0 = 0u, k1 = 42u;
    for (int t = 0; t < KSTEPS; t++) {
        uint32_t n0, n1, h0, h1, w0, w1;
        tf2x32_host(k0, k1, 0u, 0u, &n0, &n1);
        tf2x32_host(k0, k1, 0u, 1u, &h0, &h1);
        tf2x32_host(k0, k1, 0u, 2u, &w0, &w1);
        keys.kh0[t] = h0; keys.kh1[t] = h1;
        keys.kv0[t] = w0; keys.kv1[t] = w1;
        k0 = n0; k1 = n1;
    }

    cudaFuncSetAttribute(rbm_kernel, cudaFuncAttributeMaxDynamicSharedMemorySize, SMEM_BYTES);
    rbm_kernel<<<NBLK, TPB, SMEM_BYTES>>>(v_data, kern, bsc, cvec, (float*)d_out, keys);
}

// round 13
// speedup vs baseline: 1.0457x; 1.0457x over previous
#include <cuda_runtime.h>
#include <stdint.h>

// SymmetricRBM: B=65536 independent Gibbs chains, N=64 visible, ALPHA=4 hidden groups,
// circulant weights from kernel[4][64]. One warp per sample; binary states as u32-pair masks.
//
// Launch-constant tables in shared memory, PRE-SCALED by -log2(e) so accumulators
// directly produce the MUFU.EX2 argument for exp(-z):
//   Tt  [256][64]  float2 : wh pair-signature table
//   Twv4[16][256]  float4 : wv nibble table, rows quadruplicated (imm offsets)
// Bernoulli draws compare in the 2^23-scaled domain (I2F of raw mantissa bits);
// bit-identical to the u01 formulation but off the saturated alu pipe.

#define NV      64
#define ALPHA   4
#define BATCH   65536
#define KSTEPS  10
#define TPB     1024
#define WPB     32             // warps (=samples) per block
#define NBLK    (BATCH / WPB)  // 2048 blocks

#define NEG_LOG2E (-1.4426950408889634f)
#define LN2F      (0.6931471805599453f)
#define TWO23F    (8388608.0f)

// dynamic smem layout
#define T_BYTES    (256 * 64 * 8)            // float2 Tt[256][64]   = 131072
#define KT4_OFF    T_BYTES
#define KT4_BYTES  (64 * 16)                 // float4 kT4[64]       = 1024
#define W_OFF      (KT4_OFF + KT4_BYTES)
#define W_BYTES    (16 * 64 * 4)             // float  W[16][64]     = 4096
#define TWV_OFF    (W_OFF + W_BYTES)
#define TWV_BYTES  (16 * 256 * 16)           // float4 Twv4[16][256] = 65536
#define WSUM_OFF   (TWV_OFF + TWV_BYTES)
#define WSUM_BYTES (WPB * 8)
#define SMEM_BYTES (WSUM_OFF + WSUM_BYTES)   // 201984

struct GibbsKeys {
    uint32_t kh0[KSTEPS], kh1[KSTEPS];
    uint32_t kv0[KSTEPS], kv1[KSTEPS];
};

__device__ double g_partials[NBLK];

// ---------------- packed f32x2 helpers ----------------

__device__ __forceinline__ void addf32x2(uint64_t& acc, uint64_t v) {
    asm("add.rn.f32x2 %0, %0, %1;" : "+l"(acc) : "l"(v));
}
__device__ __forceinline__ void unpack2(float& lo, float& hi, uint64_t v) {
    uint32_t a, b;
    asm("mov.b64 {%0, %1}, %2;" : "=r"(a), "=r"(b) : "l"(v));
    lo = __uint_as_float(a); hi = __uint_as_float(b);
}
__device__ __forceinline__ uint64_t packf2(float lo, float hi) {
    uint64_t r;
    asm("mov.b64 %0, {%1, %2};" : "=l"(r)
        : "r"(__float_as_uint(lo)), "r"(__float_as_uint(hi)));
    return r;
}
__device__ __forceinline__ float ex2f(float x) {
    float r;
    asm("ex2.approx.f32 %0, %1;" : "=f"(r) : "f"(x));
    return r;
}

// ---------------- Threefry-2x32 (20 rounds), JAX-compatible ----------------

__host__ static uint32_t rotl32h(uint32_t x, int r) {
    return (x << r) | (x >> (32 - r));
}

__host__ static void tf2x32_host(uint32_t k0, uint32_t k1, uint32_t c0, uint32_t c1,
                                 uint32_t* o0, uint32_t* o1) {
    uint32_t ks2 = k0 ^ k1 ^ 0x1BD11BDAu;
    uint32_t x0 = c0 + k0, x1 = c1 + k1;
#define HR4A x0+=x1; x1=rotl32h(x1,13); x1^=x0; x0+=x1; x1=rotl32h(x1,15); x1^=x0; \
             x0+=x1; x1=rotl32h(x1,26); x1^=x0; x0+=x1; x1=rotl32h(x1, 6); x1^=x0;
#define HR4B x0+=x1; x1=rotl32h(x1,17); x1^=x0; x0+=x1; x1=rotl32h(x1,29); x1^=x0; \
             x0+=x1; x1=rotl32h(x1,16); x1^=x0; x0+=x1; x1=rotl32h(x1,24); x1^=x0;
    HR4A; x0 += k1;  x1 += ks2 + 1u;
    HR4B; x0 += ks2; x1 += k0  + 2u;
    HR4A; x0 += k0;  x1 += k1  + 3u;
    HR4B; x0 += k1;  x1 += ks2 + 4u;
    HR4A; x0 += ks2; x1 += k0  + 5u;
    *o0 = x0; *o1 = x1;
}
#undef HR4A
#undef HR4B

__device__ __forceinline__ uint32_t rotl32d(uint32_t x, int r) {
    return __funnelshift_l(x, x, r);
}

// counter hi word always 0; JAX partitionable random_bits -> x0 ^ x1
__device__ __forceinline__ uint32_t tf_bits(uint32_t k0, uint32_t k1, uint32_t ctr_lo) {
    uint32_t ks2 = k0 ^ k1 ^ 0x1BD11BDAu;
    uint32_t x0 = k0;
    uint32_t x1 = ctr_lo + k1;
#define R4A  x0+=x1; x1=rotl32d(x1,13); x1^=x0; x0+=x1; x1=rotl32d(x1,15); x1^=x0; \
             x0+=x1; x1=rotl32d(x1,26); x1^=x0; x0+=x1; x1=rotl32d(x1, 6); x1^=x0;
#define R4B  x0+=x1; x1=rotl32d(x1,17); x1^=x0; x0+=x1; x1=rotl32d(x1,29); x1^=x0; \
             x0+=x1; x1=rotl32d(x1,16); x1^=x0; x0+=x1; x1=rotl32d(x1,24); x1^=x0;
    R4A; x0 += k1;  x1 += ks2 + 1u;
    R4B; x0 += ks2; x1 += k0  + 2u;
    R4A; x0 += k0;  x1 += k1  + 3u;
    R4B; x0 += k1;  x1 += ks2 + 4u;
    R4A; x0 += ks2; x1 += k0  + 5u;
    return x0 ^ x1;
#undef R4A
#undef R4B
}

// ---------------- wv: circulant forward via quadruplicated nibble table ----------------
// Accumulators hold SCALED values wp = -log2e*(wv+cc).
struct WvAcc { uint64_t P0, P1, P2, P3; };

__device__ __forceinline__ WvAcc compute_wv(uint32_t lo, uint32_t hi, int lane,
                                            const unsigned char* __restrict__ TwvRaw,
                                            uint64_t CC01, uint64_t CC23) {
    // lane n (n<16) owns nibble n of (lo|hi<<32), pre-scaled to its 4096-byte row offset
    uint32_t nib = (((lane < 8) ? (lo >> (4 * lane)) : (hi >> ((4 * lane) & 31))) & 15u) << 12;

    WvAcc A; A.P0 = CC01; A.P1 = CC23; A.P2 = CC01; A.P3 = CC23;
    const unsigned char* pbase = TwvRaw + (uint32_t)(((-lane) & 63) << 4);
#pragma unroll
    for (int n = 0; n < 16; n++) {
        uint32_t rowoff = (uint32_t)__shfl_sync(0xffffffffu, (int)nib, n);
        const unsigned char* p = pbase + rowoff;
        ulonglong2 x = *(const ulonglong2*)(p + 64 * n);
        ulonglong2 y = *(const ulonglong2*)(p + 64 * n + 512);
        addf32x2(A.P0, x.x); addf32x2(A.P1, x.y);
        addf32x2(A.P2, y.x); addf32x2(A.P3, y.y);
    }
    return A;
}

__device__ __forceinline__ void unpack_wv(const WvAcc& A, float* w) {
    unpack2(w[0], w[2], A.P0);
    unpack2(w[4], w[6], A.P1);
    unpack2(w[1], w[3], A.P2);
    unpack2(w[5], w[7], A.P3);
}

// softplus sum from SCALED wp = -log2e*z:
//   softplus(z) = ln2*max(-wp,0) + log1p(2^(-|wp|)),  -|wp| = min(wp,-wp)
__device__ __forceinline__ float softplus_sum(const float* w) {
    float s = 0.0f;
#pragma unroll
    for (int q = 0; q < 8; q++) {
        float wp = w[q];
        float nw = -wp;
        float t  = ex2f(fminf(wp, nw));
        s += fmaf(fmaxf(nw, 0.0f), LN2F, log1pf(t));
    }
    return s;
}

// Bernoulli(sigmoid(z)) from raw threefry bits and scaled wp = -log2e*z.
// u = (bits>>9)*2^-23 exactly (JAX u01); test u*(1+e) < 1 in the 2^23-scaled
// domain: fma(Uf, e, Uf) < 2^23 with Uf = I2F(bits>>9). Power-of-2 scaling
// commutes with round-to-nearest -> verdict bit-identical to the u01 form.
__device__ __forceinline__ int bern_sig_bits(uint32_t bits, float wp) {
    float Uf = __uint2float_rn(bits >> 9);
    float e  = ex2f(wp);
    return fmaf(Uf, e, Uf) < TWO23F;
}

// ---------------- main kernel: one warp per batch sample, 32 samples/block ----------------

__global__ void __launch_bounds__(TPB, 1)
rbm_kernel(const float* __restrict__ v_data, const float* __restrict__ kern,
           const float* __restrict__ bsc, const float* __restrict__ cvec,
           GibbsKeys keys) {
    extern __shared__ unsigned char smem_raw[];
    float2* Tt   = (float2*)smem_raw;                  // [256][64] pair (i, i+32), SCALED
    float4* kT4  = (float4*)(smem_raw + KT4_OFF);      // [64]
    float*  W    = (float*)(smem_raw + W_OFF);         // [16][64]
    float4* Twv4 = (float4*)(smem_raw + TWV_OFF);      // [16][256] quadruplicated, SCALED
    double* wsum = (double*)(smem_raw + WSUM_OFF);     // [WPB]
    const unsigned char* TwvRaw = smem_raw + TWV_OFF;
    const unsigned char* TtRaw  = smem_raw;

    const int tid = threadIdx.x;

    // ---- phase 1: W[s][d] = sum_a bit_a(s)*k[a][d] (unscaled) and kT4[d] ----
    {
        if (tid < 16 * 64) {
            int s = tid >> 6, d = tid & 63;
            float acc = 0.0f;
#pragma unroll
            for (int a = 0; a < ALPHA; a++)
                if ((s >> a) & 1) acc += kern[a * NV + d];
            W[tid] = acc;
        }
        if (tid < 64)
            kT4[tid] = make_float4(kern[tid], kern[NV + tid], kern[2 * NV + tid], kern[3 * NV + tid]);
    }
    __syncthreads();

    // ---- phase 2a: Tt[idx8][e] (wh pair table), scaled by -log2e ----
    for (int idx = tid; idx < 256 * 64; idx += TPB) {
        int i8 = idx >> 6, e = idx & 63;
        int slo = (i8 & 1) | ((i8 >> 1) & 2) | ((i8 >> 2) & 4) | ((i8 >> 3) & 8);
        int shi = ((i8 >> 1) & 1) | ((i8 >> 2) & 2) | ((i8 >> 3) & 4) | ((i8 >> 4) & 8);
        int em1 = (e - 1) & 63;
        float x = W[slo * 64 + e] + W[shi * 64 + em1];
        float y = W[slo * 64 + (e ^ 32)] + W[shi * 64 + (em1 ^ 32)];
        Tt[idx] = make_float2(NEG_LOG2E * x, NEG_LOG2E * y);
    }

    // ---- phase 2b: Twv4[s][i] = -log2e * sum_{r in bits(s)} kT4[((i&63)+r)&63] ----
    for (int idx = tid; idx < 16 * 256; idx += TPB) {
        int s = idx >> 8, d = idx & 63;
        float4 acc = make_float4(0.f, 0.f, 0.f, 0.f);
#pragma unroll
        for (int r = 0; r < 4; r++) {
            if ((s >> r) & 1) {
                float4 k = kT4[(d + r) & 63];
                acc.x += k.x; acc.y += k.y; acc.z += k.z; acc.w += k.w;
            }
        }
        Twv4[idx] = make_float4(NEG_LOG2E * acc.x, NEG_LOG2E * acc.y,
                                NEG_LOG2E * acc.z, NEG_LOG2E * acc.w);
    }
    __syncthreads();

    const int lane = tid & 31;
    const int wid  = tid >> 5;
    const int b    = blockIdx.x * WPB + wid;

    const float bS = __ldg(bsc);
    const float sc_bS = NEG_LOG2E * bS;
    const uint64_t CC01 = packf2(NEG_LOG2E * __ldg(cvec + 0), NEG_LOG2E * __ldg(cvec + 1));
    const uint64_t CC23 = packf2(NEG_LOG2E * __ldg(cvec + 2), NEG_LOG2E * __ldg(cvec + 3));
    const uint64_t BSS  = packf2(sc_bS, sc_bS);

    // pack visible data into warp-uniform masks
    const float va = v_data[b * NV + lane];
    const float vb = v_data[b * NV + 32 + lane];
    uint32_t vlo = __ballot_sync(0xffffffffu, va > 0.5f);
    uint32_t vhi = __ballot_sync(0xffffffffu, vb > 0.5f);
    const uint32_t dlo = vlo, dhi = vhi;

    float w[8];

    // scaled wv(V_data)+cc: shared by sp_d and step 0's hidden sampling
    {
        WvAcc A = compute_wv(dlo, dhi, lane, TwvRaw, CC01, CC23);
        unpack_wv(A, w);
    }
    const float sp_d = softplus_sum(w);

    const uint32_t bb = (uint32_t)b * (ALPHA * NV) + (uint32_t)lane;  // hidden ctr base
    const uint32_t mv = (uint32_t)b * NV + (uint32_t)lane;            // visible ctr base
    const uint32_t ebOff0 = (uint32_t)(((lane - 1) & 63) << 3);       // byte offset of e within Tt row
    const int shsig = (2 * lane) & 31;                                // per-lane wh signature shift

#pragma unroll 1
    for (int t = 0; t < KSTEPS; t++) {
        // ---- sample hidden from scaled w ----
        const uint32_t kh0 = keys.kh0[t], kh1 = keys.kh1[t];
        uint32_t hlo[ALPHA], hhi[ALPHA];
#pragma unroll
        for (int a = 0; a < ALPHA; a++) {
            const uint32_t mb = bb + (uint32_t)(a * NV);
            int h0 = bern_sig_bits(tf_bits(kh0, kh1, mb),       w[a * 2 + 0]);
            int h1 = bern_sig_bits(tf_bits(kh0, kh1, mb + 32u), w[a * 2 + 1]);
            hlo[a] = __ballot_sync(0xffffffffu, h0);
            hhi[a] = __ballot_sync(0xffffffffu, h1);
        }

        // ---- per-lane wh signature (IMAD combine), pre-scaled to 512B row ----
        uint32_t s0, s1, s2, s3;
        if (lane < 16) {
            s0 = hlo[0] >> shsig; s1 = hlo[1] >> shsig;
            s2 = hlo[2] >> shsig; s3 = hlo[3] >> shsig;
        } else {
            s0 = hhi[0] >> shsig; s1 = hhi[1] >> shsig;
            s2 = hhi[2] >> shsig; s3 = hhi[3] >> shsig;
        }
        uint32_t sigOff = ((s0 & 3u) + (s1 & 3u) * 4u + (s2 & 3u) * 16u + (s3 & 3u) * 64u) * 512u;

        // ---- wh: 32 dense iterations, SHFL-broadcast row offset, dual packed accums ----
        uint64_t WHa = BSS, WHb = 0ull;  // scaled: -log2e*(wh+bS) when merged
#pragma unroll
        for (int mm = 0; mm < 32; mm += 2) {
            uint32_t ro0 = (uint32_t)__shfl_sync(0xffffffffu, (int)sigOff, mm);
            uint32_t e0  = (ebOff0 - 16u * (uint32_t)mm) & 511u;
            addf32x2(WHa, *(const uint64_t*)(TtRaw + ro0 + e0));
            uint32_t ro1 = (uint32_t)__shfl_sync(0xffffffffu, (int)sigOff, mm + 1);
            uint32_t e1  = (ebOff0 - 16u * (uint32_t)(mm + 1)) & 511u;
            addf32x2(WHb, *(const uint64_t*)(TtRaw + ro1 + e1));
        }
        addf32x2(WHa, WHb);
        float wh0, wh1;
        unpack2(wh0, wh1, WHa);

        // ---- sample visible ----
        const uint32_t kv0 = keys.kv0[t], kv1 = keys.kv1[t];
        int n0 = bern_sig_bits(tf_bits(kv0, kv1, mv),       wh0);
        int n1 = bern_sig_bits(tf_bits(kv0, kv1, mv + 32u), wh1);
        vlo = __ballot_sync(0xffffffffu, n0);
        vhi = __ballot_sync(0xffffffffu, n1);

        // ---- scaled wv of new V (next step's hidden sampling, or sp_m after t=9) ----
        WvAcc A = compute_wv(vlo, vhi, lane, TwvRaw, CC01, CC23);
        unpack_wv(A, w);
    }

    const float sp_m = softplus_sum(w);

    // fe_data - fe_model = bS*(S_m - S_d) + (SP_m - SP_d)
    float x = sp_m - sp_d;
#pragma unroll
    for (int off = 16; off; off >>= 1) x += __shfl_xor_sync(0xffffffffu, x, off);

    if (lane == 0) {
        x += bS * (float)((__popc(vlo) + __popc(vhi)) - (__popc(dlo) + __popc(dhi)));
        wsum[wid] = (double)x;
    }
    __syncthreads();
    if (tid == 0) {
        double s = 0.0;
#pragma unroll
        for (int i = 0; i < WPB; i++) s += wsum[i];
        g_partials[blockIdx.x] = s;
    }
}

// ---------------- deterministic final reduction ----------------

__global__ void __launch_bounds__(256)
reduce_kernel(float* __restrict__ out) {
    __shared__ double sh[256];
    const int tid = threadIdx.x;
    double s = 0.0;
    for (int i = tid; i < NBLK; i += 256) s += g_partials[i];  // fixed order
    sh[tid] = s;
    __syncthreads();
    for (int off = 128; off; off >>= 1) {
        if (tid < off) sh[tid] += sh[tid + off];
        __syncthreads();
    }
    if (tid == 0) out[0] = (float)(sh[0] / (double)BATCH);
}

// ---------------- launch ----------------

extern "C" void kernel_launch(void* const* d_in, const int* in_sizes, int n_in,
                              void* d_out, int out_size) {
    (void)in_sizes; (void)n_in; (void)out_size;
    const float* v_data = (const float*)d_in[0];
    const float* kern   = (const float*)d_in[1];
    const float* bsc    = (const float*)d_in[2];
    const float* cvec   = (const float*)d_in[3];

    // JAX key schedule: key(42)=(0,42); fold-like split: keys[i]=threefry(k,(0,i))
    GibbsKeys keys;
    uint32_t k0 = 0u, k1 = 42u;
    for (int t = 0; t < KSTEPS; t++) {
        uint32_t n0, n1, h0, h1, w0, w1;
        tf2x32_host(k0, k1, 0u, 0u, &n0, &n1);
        tf2x32_host(k0, k1, 0u, 1u, &h0, &h1);
        tf2x32_host(k0, k1, 0u, 2u, &w0, &w1);
        keys.kh0[t] = h0; keys.kh1[t] = h1;
        keys.kv0[t] = w0; keys.kv1[t] = w1;
        k0 = n0; k1 = n1;
    }

    cudaFuncSetAttribute(rbm_kernel, cudaFuncAttributeMaxDynamicSharedMemorySize, SMEM_BYTES);
    rbm_kernel<<<NBLK, TPB, SMEM_BYTES>>>(v_data, kern, bsc, cvec, keys);
    reduce_kernel<<<1, 256>>>((float*)d_out);
}

// round 14
// speedup vs baseline: 1.1222x; 1.0732x over previous
#include <cuda_runtime.h>
#include <stdint.h>

// SymmetricRBM: B=65536 independent Gibbs chains, N=64 visible, ALPHA=4 hidden groups,
// circulant weights from kernel[4][64]. One warp per sample; binary states as u32-pair masks.
//
// PERSISTENT version: 148 CTAs (1/SM), each looping over sample-tiles; the launch-constant
// shared-memory tables are built once per SM instead of once per block:
//   Tt  [256][64]  float2 : wh pair-signature table (scaled by -log2e)
//   Twv4[16][256]  float4 : wv nibble table, rows quadruplicated (imm offsets)
// Packed add.rn.f32x2 accumulation; biases folded into accumulator init; Bernoulli
// draws via fma(u, 2^wp, u) < 1 on the EX2 argument produced directly by the tables.

#define NV      64
#define ALPHA   4
#define BATCH   65536
#define KSTEPS  10
#define TPB     1024
#define WPB     32             // warps (=samples) per block-tile
#define NBLK    (BATCH / WPB)  // 2048 tiles
#define PGRID   148            // persistent CTAs (1 per SM)

#define NEG_LOG2E (-1.4426950408889634f)
#define LN2F      (0.6931471805599453f)

// dynamic smem layout
#define T_BYTES    (256 * 64 * 8)            // float2 Tt[256][64]   = 131072
#define KT4_OFF    T_BYTES
#define KT4_BYTES  (64 * 16)                 // float4 kT4[64]       = 1024
#define W_OFF      (KT4_OFF + KT4_BYTES)
#define W_BYTES    (16 * 64 * 4)             // float  W[16][64]     = 4096
#define TWV_OFF    (W_OFF + W_BYTES)
#define TWV_BYTES  (16 * 256 * 16)           // float4 Twv4[16][256] = 65536
#define WSUM_OFF   (TWV_OFF + TWV_BYTES)
#define WSUM_BYTES (WPB * 8)
#define SMEM_BYTES (WSUM_OFF + WSUM_BYTES)   // 201984

struct GibbsKeys {
    uint32_t kh0[KSTEPS], kh1[KSTEPS], khs[KSTEPS];  // hidden keys + precomputed ks2
    uint32_t kv0[KSTEPS], kv1[KSTEPS], kvs[KSTEPS];  // visible keys + precomputed ks2
};

__device__ double g_partials[NBLK];

// ---------------- packed f32x2 helpers ----------------

__device__ __forceinline__ void addf32x2(uint64_t& acc, uint64_t v) {
    asm("add.rn.f32x2 %0, %0, %1;" : "+l"(acc) : "l"(v));
}
__device__ __forceinline__ void unpack2(float& lo, float& hi, uint64_t v) {
    uint32_t a, b;
    asm("mov.b64 {%0, %1}, %2;" : "=r"(a), "=r"(b) : "l"(v));
    lo = __uint_as_float(a); hi = __uint_as_float(b);
}
__device__ __forceinline__ uint64_t packf2(float lo, float hi) {
    uint64_t r;
    asm("mov.b64 %0, {%1, %2};" : "=l"(r)
        : "r"(__float_as_uint(lo)), "r"(__float_as_uint(hi)));
    return r;
}
__device__ __forceinline__ float ex2f(float x) {
    float r;
    asm("ex2.approx.f32 %0, %1;" : "=f"(r) : "f"(x));
    return r;
}

// ---------------- Threefry-2x32 (20 rounds), JAX-compatible ----------------

__host__ static uint32_t rotl32h(uint32_t x, int r) {
    return (x << r) | (x >> (32 - r));
}

__host__ static void tf2x32_host(uint32_t k0, uint32_t k1, uint32_t c0, uint32_t c1,
                                 uint32_t* o0, uint32_t* o1) {
    uint32_t ks2 = k0 ^ k1 ^ 0x1BD11BDAu;
    uint32_t x0 = c0 + k0, x1 = c1 + k1;
#define HR4A x0+=x1; x1=rotl32h(x1,13); x1^=x0; x0+=x1; x1=rotl32h(x1,15); x1^=x0; \
             x0+=x1; x1=rotl32h(x1,26); x1^=x0; x0+=x1; x1=rotl32h(x1, 6); x1^=x0;
#define HR4B x0+=x1; x1=rotl32h(x1,17); x1^=x0; x0+=x1; x1=rotl32h(x1,29); x1^=x0; \
             x0+=x1; x1=rotl32h(x1,16); x1^=x0; x0+=x1; x1=rotl32h(x1,24); x1^=x0;
    HR4A; x0 += k1;  x1 += ks2 + 1u;
    HR4B; x0 += ks2; x1 += k0  + 2u;
    HR4A; x0 += k0;  x1 += k1  + 3u;
    HR4B; x0 += k1;  x1 += ks2 + 4u;
    HR4A; x0 += ks2; x1 += k0  + 5u;
    *o0 = x0; *o1 = x1;
}
#undef HR4A
#undef HR4B

__device__ __forceinline__ uint32_t rotl32d(uint32_t x, int r) {
    return __funnelshift_l(x, x, r);
}

// counter hi word always 0; caller passes x1 = ctr + k1 (hoisted; integer-associative,
// bit-identical). JAX partitionable random_bits -> x0 ^ x1.
__device__ __forceinline__ uint32_t tf_bits_x1(uint32_t k0, uint32_t k1, uint32_t ks2,
                                               uint32_t x1) {
    uint32_t x0 = k0;
#define R4A  x0+=x1; x1=rotl32d(x1,13); x1^=x0; x0+=x1; x1=rotl32d(x1,15); x1^=x0; \
             x0+=x1; x1=rotl32d(x1,26); x1^=x0; x0+=x1; x1=rotl32d(x1, 6); x1^=x0;
#define R4B  x0+=x1; x1=rotl32d(x1,17); x1^=x0; x0+=x1; x1=rotl32d(x1,29); x1^=x0; \
             x0+=x1; x1=rotl32d(x1,16); x1^=x0; x0+=x1; x1=rotl32d(x1,24); x1^=x0;
    R4A; x0 += k1;  x1 += ks2 + 1u;
    R4B; x0 += ks2; x1 += k0  + 2u;
    R4A; x0 += k0;  x1 += k1  + 3u;
    R4B; x0 += k1;  x1 += ks2 + 4u;
    R4A; x0 += ks2; x1 += k0  + 5u;
    return x0 ^ x1;
#undef R4A
#undef R4B
}

__device__ __forceinline__ float u01(uint32_t bits) {
    return __uint_as_float((bits >> 9) | 0x3f800000u) - 1.0f;
}

// ---------------- wv: circulant forward via quadruplicated nibble table ----------------
// Accumulators hold SCALED values wp = -log2e*(wv+cc).
struct WvAcc { uint64_t P0, P1, P2, P3; };

__device__ __forceinline__ WvAcc compute_wv(uint32_t lo, uint32_t hi, int lane,
                                            const unsigned char* __restrict__ TwvRaw,
                                            uint64_t CC01, uint64_t CC23) {
    // lane n (n<16) owns nibble n of (lo|hi<<32), pre-scaled to its 4096-byte row offset
    uint32_t nib = (((lane < 8) ? (lo >> (4 * lane)) : (hi >> ((4 * lane) & 31))) & 15u) << 12;

    WvAcc A; A.P0 = CC01; A.P1 = CC23; A.P2 = CC01; A.P3 = CC23;
    const unsigned char* pbase = TwvRaw + (uint32_t)(((-lane) & 63) << 4);
#pragma unroll
    for (int n = 0; n < 16; n++) {
        uint32_t rowoff = (uint32_t)__shfl_sync(0xffffffffu, (int)nib, n);
        const unsigned char* p = pbase + rowoff;
        ulonglong2 x = *(const ulonglong2*)(p + 64 * n);
        ulonglong2 y = *(const ulonglong2*)(p + 64 * n + 512);
        addf32x2(A.P0, x.x); addf32x2(A.P1, x.y);
        addf32x2(A.P2, y.x); addf32x2(A.P3, y.y);
    }
    return A;
}

__device__ __forceinline__ void unpack_wv(const WvAcc& A, float* w) {
    unpack2(w[0], w[2], A.P0);
    unpack2(w[4], w[6], A.P1);
    unpack2(w[1], w[3], A.P2);
    unpack2(w[5], w[7], A.P3);
}

// softplus sum from SCALED wp = -log2e*z:
//   softplus(z) = ln2*max(-wp,0) + log1p(2^(-|wp|)),  -|wp| = min(wp,-wp)
__device__ __forceinline__ float softplus_sum(const float* w) {
    float s = 0.0f;
#pragma unroll
    for (int q = 0; q < 8; q++) {
        float wp = w[q];
        float nw = -wp;
        float t  = ex2f(fminf(wp, nw));
        s += fmaf(fmaxf(nw, 0.0f), LN2F, log1pf(t));
    }
    return s;
}

// Bernoulli(sigmoid(z)) from scaled wp = -log2e*z: e = 2^wp; u < 1/(1+e) <=> u*e+u < 1
__device__ __forceinline__ int bern_sig(float u, float wp) {
    float e = ex2f(wp);
    return fmaf(u, e, u) < 1.0f;
}

// ---------------- persistent kernel: 148 CTAs, tile loop over 2048 sample-groups ----------------

__global__ void __launch_bounds__(TPB, 1)
rbm_kernel(const float* __restrict__ v_data, const float* __restrict__ kern,
           const float* __restrict__ bsc, const float* __restrict__ cvec,
           GibbsKeys keys) {
    extern __shared__ unsigned char smem_raw[];
    float2* Tt   = (float2*)smem_raw;                  // [256][64] pair (i, i+32), SCALED
    float4* kT4  = (float4*)(smem_raw + KT4_OFF);      // [64]
    float*  W    = (float*)(smem_raw + W_OFF);         // [16][64]
    float4* Twv4 = (float4*)(smem_raw + TWV_OFF);      // [16][256] quadruplicated, SCALED
    double* wsum = (double*)(smem_raw + WSUM_OFF);     // [WPB]
    const unsigned char* TwvRaw = smem_raw + TWV_OFF;
    const unsigned char* TtRaw  = smem_raw;

    const int tid = threadIdx.x;

    // ---- table build: ONCE per persistent CTA ----
    {
        if (tid < 16 * 64) {
            int s = tid >> 6, d = tid & 63;
            float acc = 0.0f;
#pragma unroll
            for (int a = 0; a < ALPHA; a++)
                if ((s >> a) & 1) acc += kern[a * NV + d];
            W[tid] = acc;
        }
        if (tid < 64)
            kT4[tid] = make_float4(kern[tid], kern[NV + tid], kern[2 * NV + tid], kern[3 * NV + tid]);
    }
    __syncthreads();

    // Tt[idx8][e] (wh pair table), scaled by -log2e
    for (int idx = tid; idx < 256 * 64; idx += TPB) {
        int i8 = idx >> 6, e = idx & 63;
        int slo = (i8 & 1) | ((i8 >> 1) & 2) | ((i8 >> 2) & 4) | ((i8 >> 3) & 8);
        int shi = ((i8 >> 1) & 1) | ((i8 >> 2) & 2) | ((i8 >> 3) & 4) | ((i8 >> 4) & 8);
        int em1 = (e - 1) & 63;
        float x = W[slo * 64 + e] + W[shi * 64 + em1];
        float y = W[slo * 64 + (e ^ 32)] + W[shi * 64 + (em1 ^ 32)];
        Tt[idx] = make_float2(NEG_LOG2E * x, NEG_LOG2E * y);
    }

    // Twv4[s][i] = -log2e * sum_{r in bits(s)} kT4[((i&63)+r)&63], quadruplicated rows
    for (int idx = tid; idx < 16 * 256; idx += TPB) {
        int s = idx >> 8, d = idx & 63;
        float4 acc = make_float4(0.f, 0.f, 0.f, 0.f);
#pragma unroll
        for (int r = 0; r < 4; r++) {
            if ((s >> r) & 1) {
                float4 k = kT4[(d + r) & 63];
                acc.x += k.x; acc.y += k.y; acc.z += k.z; acc.w += k.w;
            }
        }
        Twv4[idx] = make_float4(NEG_LOG2E * acc.x, NEG_LOG2E * acc.y,
                                NEG_LOG2E * acc.z, NEG_LOG2E * acc.w);
    }
    __syncthreads();

    const int lane = tid & 31;
    const int wid  = tid >> 5;

    const float bS = __ldg(bsc);
    const float sc_bS = NEG_LOG2E * bS;
    const uint64_t CC01 = packf2(NEG_LOG2E * __ldg(cvec + 0), NEG_LOG2E * __ldg(cvec + 1));
    const uint64_t CC23 = packf2(NEG_LOG2E * __ldg(cvec + 2), NEG_LOG2E * __ldg(cvec + 3));
    const uint64_t BSS  = packf2(sc_bS, sc_bS);

    const uint32_t ebOff0 = (uint32_t)(((lane - 1) & 63) << 3);  // byte offset of e in Tt row
    const int shsig = (2 * lane) & 31;                           // per-lane wh signature shift

    // ---- persistent tile loop ----
    for (int tile = blockIdx.x; tile < NBLK; tile += PGRID) {
        const int b = tile * WPB + wid;

        // pack visible data into warp-uniform masks
        const float va = v_data[b * NV + lane];
        const float vb = v_data[b * NV + 32 + lane];
        uint32_t vlo = __ballot_sync(0xffffffffu, va > 0.5f);
        uint32_t vhi = __ballot_sync(0xffffffffu, vb > 0.5f);
        const uint32_t dlo = vlo, dhi = vhi;

        float w[8];

        // scaled wv(V_data)+cc: shared by sp_d and step 0's hidden sampling
        {
            WvAcc A = compute_wv(dlo, dhi, lane, TwvRaw, CC01, CC23);
            unpack_wv(A, w);
        }
        const float sp_d = softplus_sum(w);

        const uint32_t bb = (uint32_t)b * (ALPHA * NV) + (uint32_t)lane;  // hidden ctr base
        const uint32_t mv = (uint32_t)b * NV + (uint32_t)lane;            // visible ctr base

#pragma unroll 1
        for (int t = 0; t < KSTEPS; t++) {
            // ---- sample hidden from scaled w ----
            const uint32_t kh0 = keys.kh0[t], kh1 = keys.kh1[t], khs = keys.khs[t];
            const uint32_t bbk = bb + kh1;  // counter pre-added with k1 (hoisted)
            uint32_t hlo[ALPHA], hhi[ALPHA];
#pragma unroll
            for (int a = 0; a < ALPHA; a++) {
                float u0 = u01(tf_bits_x1(kh0, kh1, khs, bbk + (uint32_t)(a * NV)));
                float u1 = u01(tf_bits_x1(kh0, kh1, khs, bbk + (uint32_t)(a * NV + 32)));
                int h0 = bern_sig(u0, w[a * 2 + 0]);
                int h1 = bern_sig(u1, w[a * 2 + 1]);
                hlo[a] = __ballot_sync(0xffffffffu, h0);
                hhi[a] = __ballot_sync(0xffffffffu, h1);
            }

            // ---- per-lane wh signature (IMAD combine), pre-scaled to 512B row ----
            uint32_t s0, s1, s2, s3;
            if (lane < 16) {
                s0 = hlo[0] >> shsig; s1 = hlo[1] >> shsig;
                s2 = hlo[2] >> shsig; s3 = hlo[3] >> shsig;
            } else {
                s0 = hhi[0] >> shsig; s1 = hhi[1] >> shsig;
                s2 = hhi[2] >> shsig; s3 = hhi[3] >> shsig;
            }
            uint32_t sigOff = ((s0 & 3u) + (s1 & 3u) * 4u + (s2 & 3u) * 16u + (s3 & 3u) * 64u) * 512u;

            // ---- wh: 32 dense iterations, SHFL-broadcast row offset, dual packed accums ----
            uint64_t WHa = BSS, WHb = 0ull;  // scaled: -log2e*(wh+bS) when merged
#pragma unroll
            for (int mm = 0; mm < 32; mm += 2) {
                uint32_t ro0 = (uint32_t)__shfl_sync(0xffffffffu, (int)sigOff, mm);
                uint32_t e0  = (ebOff0 - 16u * (uint32_t)mm) & 511u;
                addf32x2(WHa, *(const uint64_t*)(TtRaw + ro0 + e0));
                uint32_t ro1 = (uint32_t)__shfl_sync(0xffffffffu, (int)sigOff, mm + 1);
                uint32_t e1  = (ebOff0 - 16u * (uint32_t)(mm + 1)) & 511u;
                addf32x2(WHb, *(const uint64_t*)(TtRaw + ro1 + e1));
            }
            addf32x2(WHa, WHb);
            float wh0, wh1;
            unpack2(wh0, wh1, WHa);

            // ---- sample visible ----
            const uint32_t kv0 = keys.kv0[t], kv1 = keys.kv1[t], kvs = keys.kvs[t];
            const uint32_t mvk = mv + kv1;
            float u0 = u01(tf_bits_x1(kv0, kv1, kvs, mvk));
            float u1 = u01(tf_bits_x1(kv0, kv1, kvs, mvk + 32u));
            int n0 = bern_sig(u0, wh0);
            int n1 = bern_sig(u1, wh1);
            vlo = __ballot_sync(0xffffffffu, n0);
            vhi = __ballot_sync(0xffffffffu, n1);

            // ---- scaled wv of new V (next step's hidden sampling, or sp_m after t=9) ----
            WvAcc A = compute_wv(vlo, vhi, lane, TwvRaw, CC01, CC23);
            unpack_wv(A, w);
        }

        const float sp_m = softplus_sum(w);

        // fe_data - fe_model = bS*(S_m - S_d) + (SP_m - SP_d)
        float x = sp_m - sp_d;
#pragma unroll
        for (int off = 16; off; off >>= 1) x += __shfl_xor_sync(0xffffffffu, x, off);

        if (lane == 0) {
            x += bS * (float)((__popc(vlo) + __popc(vhi)) - (__popc(dlo) + __popc(dhi)));
            wsum[wid] = (double)x;
        }
        __syncthreads();
        if (tid == 0) {
            double s = 0.0;
#pragma unroll
            for (int i = 0; i < WPB; i++) s += wsum[i];
            g_partials[tile] = s;
        }
        __syncthreads();  // WAR: wsum reused next tile
    }
}

// ---------------- deterministic final reduction ----------------

__global__ void __launch_bounds__(256)
reduce_kernel(float* __restrict__ out) {
    __shared__ double sh[256];
    const int tid = threadIdx.x;
    double s = 0.0;
    for (int i = tid; i < NBLK; i += 256) s += g_partials[i];  // fixed order
    sh[tid] = s;
    __syncthreads();
    for (int off = 128; off; off >>= 1) {
        if (tid < off) sh[tid] += sh[tid + off];
        __syncthreads();
    }
    if (tid == 0) out[0] = (float)(sh[0] / (double)BATCH);
}

// ---------------- launch ----------------

extern "C" void kernel_launch(void* const* d_in, const int* in_sizes, int n_in,
                              void* d_out, int out_size) {
    (void)in_sizes; (void)n_in; (void)out_size;
    const float* v_data = (const float*)d_in[0];
    const float* kern   = (const float*)d_in[1];
    const float* bsc    = (const float*)d_in[2];
    const float* cvec   = (const float*)d_in[3];

    // JAX key schedule: key(42)=(0,42); fold-like split: keys[i]=threefry(k,(0,i))
    GibbsKeys keys;
    uint32_t k0 = 0u, k1 = 42u;
    for (int t = 0; t < KSTEPS; t++) {
        uint32_t n0, n1, h0, h1, w0, w1;
        tf2x32_host(k0, k1, 0u, 0u, &n0, &n1);
        tf2x32_host(k0, k1, 0u, 1u, &h0, &h1);
        tf2x32_host(k0, k1, 0u, 2u, &w0, &w1);
        keys.kh0[t] = h0; keys.kh1[t] = h1; keys.khs[t] = h0 ^ h1 ^ 0x1BD11BDAu;
        keys.kv0[t] = w0; keys.kv1[t] = w1; keys.kvs[t] = w0 ^ w1 ^ 0x1BD11BDAu;
        k0 = n0; k1 = n1;
    }

    cudaFuncSetAttribute(rbm_kernel, cudaFuncAttributeMaxDynamicSharedMemorySize, SMEM_BYTES);
    rbm_kernel<<<PGRID, TPB, SMEM_BYTES>>>(v_data, kern, bsc, cvec, keys);
    reduce_kernel<<<1, 256>>>((float*)d_out);
}

// round 15
// speedup vs baseline: 1.1322x; 1.0089x over previous
#include <cuda_runtime.h>
#include <stdint.h>

// SymmetricRBM: B=65536 independent Gibbs chains, N=64 visible, ALPHA=4 hidden groups,
// circulant weights from kernel[4][64]. One warp per sample; binary states as u32-pair masks.
//
// PERSISTENT, barrier-free: 148 CTAs (1/SM); tables built once per SM; each WARP then
// independently loops over its samples (stride 4736) with no block synchronization.
// Threefry integer adds are emitted as IMAD (mad.lo with runtime 'one') to move them
// off the saturated alu pipe onto the fma pipe; key-injection constants folded host-side.
//   Tt  [256][64]  float2 : wh pair-signature table (scaled by -log2e)
//   Twv4[16][256]  float4 : wv nibble table, rows quadruplicated (imm offsets)

#define NV      64
#define ALPHA   4
#define BATCH   65536
#define KSTEPS  10
#define TPB     1024
#define WPB     32             // warps per CTA
#define PGRID   148            // persistent CTAs (1 per SM)
#define GWARPS  (PGRID * WPB)  // 4736 global warps

#define NEG_LOG2E (-1.4426950408889634f)
#define LN2F      (0.6931471805599453f)

// dynamic smem layout
#define T_BYTES    (256 * 64 * 8)            // float2 Tt[256][64]   = 131072
#define KT4_OFF    T_BYTES
#define KT4_BYTES  (64 * 16)                 // float4 kT4[64]       = 1024
#define W_OFF      (KT4_OFF + KT4_BYTES)
#define W_BYTES    (16 * 64 * 4)             // float  W[16][64]     = 4096
#define TWV_OFF    (W_OFF + W_BYTES)
#define TWV_BYTES  (16 * 256 * 16)           // float4 Twv4[16][256] = 65536
#define SMEM_BYTES (TWV_OFF + TWV_BYTES)     // 201728

struct TFKey {
    uint32_t k0, k1, ks2;          // key words + ks2
    uint32_t i1, i2, i3, i4, i5;   // folded injections: ks2+1, k0+2, k1+3, ks2+4, k0+5
};
struct GibbsKeys { TFKey kh[KSTEPS], kv[KSTEPS]; };

__device__ double g_warp[GWARPS];

// ---------------- packed f32x2 helpers ----------------

__device__ __forceinline__ void addf32x2(uint64_t& acc, uint64_t v) {
    asm("add.rn.f32x2 %0, %0, %1;" : "+l"(acc) : "l"(v));
}
__device__ __forceinline__ void unpack2(float& lo, float& hi, uint64_t v) {
    uint32_t a, b;
    asm("mov.b64 {%0, %1}, %2;" : "=r"(a), "=r"(b) : "l"(v));
    lo = __uint_as_float(a); hi = __uint_as_float(b);
}
__device__ __forceinline__ uint64_t packf2(float lo, float hi) {
    uint64_t r;
    asm("mov.b64 %0, {%1, %2};" : "=l"(r)
        : "r"(__float_as_uint(lo)), "r"(__float_as_uint(hi)));
    return r;
}
__device__ __forceinline__ float ex2f(float x) {
    float r;
    asm("ex2.approx.f32 %0, %1;" : "=f"(r) : "f"(x));
    return r;
}

// integer add routed to the fma pipe: a*one + b (one is a runtime kernel arg,
// so ptxas cannot strength-reduce the IMAD back to IADD3 on the alu pipe)
__device__ __forceinline__ uint32_t imad1(uint32_t a, uint32_t one, uint32_t b) {
    uint32_t r;
    asm("mad.lo.u32 %0, %1, %2, %3;" : "=r"(r) : "r"(a), "r"(one), "r"(b));
    return r;
}

// ---------------- Threefry-2x32 (20 rounds), JAX-compatible ----------------

__host__ static uint32_t rotl32h(uint32_t x, int r) {
    return (x << r) | (x >> (32 - r));
}

__host__ static void tf2x32_host(uint32_t k0, uint32_t k1, uint32_t c0, uint32_t c1,
                                 uint32_t* o0, uint32_t* o1) {
    uint32_t ks2 = k0 ^ k1 ^ 0x1BD11BDAu;
    uint32_t x0 = c0 + k0, x1 = c1 + k1;
#define HR4A x0+=x1; x1=rotl32h(x1,13); x1^=x0; x0+=x1; x1=rotl32h(x1,15); x1^=x0; \
             x0+=x1; x1=rotl32h(x1,26); x1^=x0; x0+=x1; x1=rotl32h(x1, 6); x1^=x0;
#define HR4B x0+=x1; x1=rotl32h(x1,17); x1^=x0; x0+=x1; x1=rotl32h(x1,29); x1^=x0; \
             x0+=x1; x1=rotl32h(x1,16); x1^=x0; x0+=x1; x1=rotl32h(x1,24); x1^=x0;
    HR4A; x0 += k1;  x1 += ks2 + 1u;
    HR4B; x0 += ks2; x1 += k0  + 2u;
    HR4A; x0 += k0;  x1 += k1  + 3u;
    HR4B; x0 += k1;  x1 += ks2 + 4u;
    HR4A; x0 += ks2; x1 += k0  + 5u;
    *o0 = x0; *o1 = x1;
}
#undef HR4A
#undef HR4B

__device__ __forceinline__ uint32_t rotl32d(uint32_t x, int r) {
    return __funnelshift_l(x, x, r);
}

// counter hi word always 0; caller passes x1 = ctr + k1 (hoisted). Adds go through
// imad1 (fma pipe); SHF/LOP3 stay on alu. Integer result identical to the reference.
__device__ __forceinline__ uint32_t tf_bits_x1(const TFKey& K, uint32_t x1, uint32_t one) {
    uint32_t x0 = K.k0;
#define R4A  x0=imad1(x1,one,x0); x1=rotl32d(x1,13); x1^=x0; \
             x0=imad1(x1,one,x0); x1=rotl32d(x1,15); x1^=x0; \
             x0=imad1(x1,one,x0); x1=rotl32d(x1,26); x1^=x0; \
             x0=imad1(x1,one,x0); x1=rotl32d(x1, 6); x1^=x0;
#define R4B  x0=imad1(x1,one,x0); x1=rotl32d(x1,17); x1^=x0; \
             x0=imad1(x1,one,x0); x1=rotl32d(x1,29); x1^=x0; \
             x0=imad1(x1,one,x0); x1=rotl32d(x1,16); x1^=x0; \
             x0=imad1(x1,one,x0); x1=rotl32d(x1,24); x1^=x0;
    R4A; x0 = imad1(K.k1,  one, x0); x1 = imad1(K.i1, one, x1);
    R4B; x0 = imad1(K.ks2, one, x0); x1 = imad1(K.i2, one, x1);
    R4A; x0 = imad1(K.k0,  one, x0); x1 = imad1(K.i3, one, x1);
    R4B; x0 = imad1(K.k1,  one, x0); x1 = imad1(K.i4, one, x1);
    R4A; x0 = imad1(K.ks2, one, x0); x1 = imad1(K.i5, one, x1);
    return x0 ^ x1;
#undef R4A
#undef R4B
}

__device__ __forceinline__ float u01(uint32_t bits) {
    return __uint_as_float((bits >> 9) | 0x3f800000u) - 1.0f;
}

// ---------------- wv: circulant forward via quadruplicated nibble table ----------------
// Accumulators hold SCALED values wp = -log2e*(wv+cc).
struct WvAcc { uint64_t P0, P1, P2, P3; };

__device__ __forceinline__ WvAcc compute_wv(uint32_t lo, uint32_t hi, int lane,
                                            const unsigned char* __restrict__ TwvRaw,
                                            uint64_t CC01, uint64_t CC23) {
    // lane n (n<16) owns nibble n of (lo|hi<<32), pre-scaled to its 4096-byte row offset
    uint32_t nib = (((lane < 8) ? (lo >> (4 * lane)) : (hi >> ((4 * lane) & 31))) & 15u) << 12;

    WvAcc A; A.P0 = CC01; A.P1 = CC23; A.P2 = CC01; A.P3 = CC23;
    const unsigned char* pbase = TwvRaw + (uint32_t)(((-lane) & 63) << 4);
#pragma unroll
    for (int n = 0; n < 16; n++) {
        uint32_t rowoff = (uint32_t)__shfl_sync(0xffffffffu, (int)nib, n);
        const unsigned char* p = pbase + rowoff;
        ulonglong2 x = *(const ulonglong2*)(p + 64 * n);
        ulonglong2 y = *(const ulonglong2*)(p + 64 * n + 512);
        addf32x2(A.P0, x.x); addf32x2(A.P1, x.y);
        addf32x2(A.P2, y.x); addf32x2(A.P3, y.y);
    }
    return A;
}

__device__ __forceinline__ void unpack_wv(const WvAcc& A, float* w) {
    unpack2(w[0], w[2], A.P0);
    unpack2(w[4], w[6], A.P1);
    unpack2(w[1], w[3], A.P2);
    unpack2(w[5], w[7], A.P3);
}

// softplus sum from SCALED wp = -log2e*z:
//   softplus(z) = ln2*max(-wp,0) + log1p(2^(-|wp|)),  -|wp| = min(wp,-wp)
__device__ __forceinline__ float softplus_sum(const float* w) {
    float s = 0.0f;
#pragma unroll
    for (int q = 0; q < 8; q++) {
        float wp = w[q];
        float nw = -wp;
        float t  = ex2f(fminf(wp, nw));
        s += fmaf(fmaxf(nw, 0.0f), LN2F, log1pf(t));
    }
    return s;
}

// Bernoulli(sigmoid(z)) from scaled wp = -log2e*z: e = 2^wp; u < 1/(1+e) <=> u*e+u < 1
__device__ __forceinline__ int bern_sig(float u, float wp) {
    float e = ex2f(wp);
    return fmaf(u, e, u) < 1.0f;
}

// ---------------- persistent kernel: per-warp independent sample loop ----------------

__global__ void __launch_bounds__(TPB, 1)
rbm_kernel(const float* __restrict__ v_data, const float* __restrict__ kern,
           const float* __restrict__ bsc, const float* __restrict__ cvec,
           GibbsKeys keys, uint32_t one) {
    extern __shared__ unsigned char smem_raw[];
    float2* Tt   = (float2*)smem_raw;                  // [256][64] pair (i, i+32), SCALED
    float4* kT4  = (float4*)(smem_raw + KT4_OFF);      // [64]
    float*  W    = (float*)(smem_raw + W_OFF);         // [16][64]
    float4* Twv4 = (float4*)(smem_raw + TWV_OFF);      // [16][256] quadruplicated, SCALED
    const unsigned char* TwvRaw = smem_raw + TWV_OFF;
    const unsigned char* TtRaw  = smem_raw;

    const int tid = threadIdx.x;

    // ---- table build: ONCE per persistent CTA ----
    {
        if (tid < 16 * 64) {
            int s = tid >> 6, d = tid & 63;
            float acc = 0.0f;
#pragma unroll
            for (int a = 0; a < ALPHA; a++)
                if ((s >> a) & 1) acc += kern[a * NV + d];
            W[tid] = acc;
        }
        if (tid < 64)
            kT4[tid] = make_float4(kern[tid], kern[NV + tid], kern[2 * NV + tid], kern[3 * NV + tid]);
    }
    __syncthreads();

    // Tt[idx8][e] (wh pair table), scaled by -log2e
    for (int idx = tid; idx < 256 * 64; idx += TPB) {
        int i8 = idx >> 6, e = idx & 63;
        int slo = (i8 & 1) | ((i8 >> 1) & 2) | ((i8 >> 2) & 4) | ((i8 >> 3) & 8);
        int shi = ((i8 >> 1) & 1) | ((i8 >> 2) & 2) | ((i8 >> 3) & 4) | ((i8 >> 4) & 8);
        int em1 = (e - 1) & 63;
        float x = W[slo * 64 + e] + W[shi * 64 + em1];
        float y = W[slo * 64 + (e ^ 32)] + W[shi * 64 + (em1 ^ 32)];
        Tt[idx] = make_float2(NEG_LOG2E * x, NEG_LOG2E * y);
    }

    // Twv4[s][i] = -log2e * sum_{r in bits(s)} kT4[((i&63)+r)&63], quadruplicated rows
    for (int idx = tid; idx < 16 * 256; idx += TPB) {
        int s = idx >> 8, d = idx & 63;
        float4 acc = make_float4(0.f, 0.f, 0.f, 0.f);
#pragma unroll
        for (int r = 0; r < 4; r++) {
            if ((s >> r) & 1) {
                float4 k = kT4[(d + r) & 63];
                acc.x += k.x; acc.y += k.y; acc.z += k.z; acc.w += k.w;
            }
        }
        Twv4[idx] = make_float4(NEG_LOG2E * acc.x, NEG_LOG2E * acc.y,
                                NEG_LOG2E * acc.z, NEG_LOG2E * acc.w);
    }
    __syncthreads();
    // Tables are read-only from here on: warps proceed fully independently.

    const int lane = tid & 31;
    const int wid  = tid >> 5;
    const int gw   = blockIdx.x * WPB + wid;  // global warp id, 0..GWARPS-1

    const float bS = __ldg(bsc);
    const float sc_bS = NEG_LOG2E * bS;
    const uint64_t CC01 = packf2(NEG_LOG2E * __ldg(cvec + 0), NEG_LOG2E * __ldg(cvec + 1));
    const uint64_t CC23 = packf2(NEG_LOG2E * __ldg(cvec + 2), NEG_LOG2E * __ldg(cvec + 3));
    const uint64_t BSS  = packf2(sc_bS, sc_bS);

    const uint32_t ebOff0 = (uint32_t)(((lane - 1) & 63) << 3);  // byte offset of e in Tt row
    const int shsig = (2 * lane) & 31;                           // per-lane wh signature shift

    double acc = 0.0;  // warp-uniform running sum of (fe_data - fe_model)

    // ---- per-warp sample loop (no block synchronization) ----
    for (int b = gw; b < BATCH; b += GWARPS) {
        // pack visible data into warp-uniform masks
        const float va = v_data[b * NV + lane];
        const float vb = v_data[b * NV + 32 + lane];
        uint32_t vlo = __ballot_sync(0xffffffffu, va > 0.5f);
        uint32_t vhi = __ballot_sync(0xffffffffu, vb > 0.5f);
        const uint32_t dlo = vlo, dhi = vhi;

        float w[8];

        // scaled wv(V_data)+cc: shared by sp_d and step 0's hidden sampling
        {
            WvAcc A = compute_wv(dlo, dhi, lane, TwvRaw, CC01, CC23);
            unpack_wv(A, w);
        }
        const float sp_d = softplus_sum(w);

        const uint32_t bb = (uint32_t)b * (ALPHA * NV) + (uint32_t)lane;  // hidden ctr base
        const uint32_t mv = (uint32_t)b * NV + (uint32_t)lane;            // visible ctr base

#pragma unroll 1
        for (int t = 0; t < KSTEPS; t++) {
            // ---- sample hidden from scaled w ----
            const TFKey& KH = keys.kh[t];
            const uint32_t bbk = bb + KH.k1;  // counter pre-added with k1 (hoisted)
            uint32_t hlo[ALPHA], hhi[ALPHA];
#pragma unroll
            for (int a = 0; a < ALPHA; a++) {
                float u0 = u01(tf_bits_x1(KH, bbk + (uint32_t)(a * NV), one));
                float u1 = u01(tf_bits_x1(KH, bbk + (uint32_t)(a * NV + 32), one));
                int h0 = bern_sig(u0, w[a * 2 + 0]);
                int h1 = bern_sig(u1, w[a * 2 + 1]);
                hlo[a] = __ballot_sync(0xffffffffu, h0);
                hhi[a] = __ballot_sync(0xffffffffu, h1);
            }

            // ---- per-lane wh signature (IMAD combine), pre-scaled to 512B row ----
            uint32_t s0, s1, s2, s3;
            if (lane < 16) {
                s0 = hlo[0] >> shsig; s1 = hlo[1] >> shsig;
                s2 = hlo[2] >> shsig; s3 = hlo[3] >> shsig;
            } else {
                s0 = hhi[0] >> shsig; s1 = hhi[1] >> shsig;
                s2 = hhi[2] >> shsig; s3 = hhi[3] >> shsig;
            }
            uint32_t sigOff = ((s0 & 3u) + (s1 & 3u) * 4u + (s2 & 3u) * 16u + (s3 & 3u) * 64u) * 512u;

            // ---- wh: 32 dense iterations, SHFL-broadcast row offset, dual packed accums ----
            uint64_t WHa = BSS, WHb = 0ull;  // scaled: -log2e*(wh+bS) when merged
#pragma unroll
            for (int mm = 0; mm < 32; mm += 2) {
                uint32_t ro0 = (uint32_t)__shfl_sync(0xffffffffu, (int)sigOff, mm);
                uint32_t e0  = (ebOff0 - 16u * (uint32_t)mm) & 511u;
                addf32x2(WHa, *(const uint64_t*)(TtRaw + ro0 + e0));
                uint32_t ro1 = (uint32_t)__shfl_sync(0xffffffffu, (int)sigOff, mm + 1);
                uint32_t e1  = (ebOff0 - 16u * (uint32_t)(mm + 1)) & 511u;
                addf32x2(WHb, *(const uint64_t*)(TtRaw + ro1 + e1));
            }
            addf32x2(WHa, WHb);
            float wh0, wh1;
            unpack2(wh0, wh1, WHa);

            // ---- sample visible ----
            const TFKey& KV = keys.kv[t];
            const uint32_t mvk = mv + KV.k1;
            float u0 = u01(tf_bits_x1(KV, mvk, one));
            float u1 = u01(tf_bits_x1(KV, mvk + 32u, one));
            int n0 = bern_sig(u0, wh0);
            int n1 = bern_sig(u1, wh1);
            vlo = __ballot_sync(0xffffffffu, n0);
            vhi = __ballot_sync(0xffffffffu, n1);

            // ---- scaled wv of new V (next step's hidden sampling, or sp_m after t=9) ----
            WvAcc A = compute_wv(vlo, vhi, lane, TwvRaw, CC01, CC23);
            unpack_wv(A, w);
        }

        const float sp_m = softplus_sum(w);

        // fe_data - fe_model = bS*(S_m - S_d) + (SP_m - SP_d)
        float x = sp_m - sp_d;
#pragma unroll
        for (int off = 16; off; off >>= 1) x += __shfl_xor_sync(0xffffffffu, x, off);
        x += bS * (float)((__popc(vlo) + __popc(vhi)) - (__popc(dlo) + __popc(dhi)));
        acc += (double)x;  // fixed per-warp order: b, b+GWARPS, ...
    }

    if (lane == 0) g_warp[gw] = acc;
}

// ---------------- deterministic final reduction over 4736 warp partials ----------------

__global__ void __launch_bounds__(1024)
reduce_kernel(float* __restrict__ out) {
    __shared__ double sh[1024];
    const int tid = threadIdx.x;
    double s = 0.0;
    for (int i = tid; i < GWARPS; i += 1024) s += g_warp[i];  // fixed order
    sh[tid] = s;
    __syncthreads();
    for (int off = 512; off; off >>= 1) {
        if (tid < off) sh[tid] += sh[tid + off];
        __syncthreads();
    }
    if (tid == 0) out[0] = (float)(sh[0] / (double)BATCH);
}

// ---------------- launch ----------------

extern "C" void kernel_launch(void* const* d_in, const int* in_sizes, int n_in,
                              void* d_out, int out_size) {
    (void)in_sizes; (void)n_in; (void)out_size;
    const float* v_data = (const float*)d_in[0];
    const float* kern   = (const float*)d_in[1];
    const float* bsc    = (const float*)d_in[2];
    const float* cvec   = (const float*)d_in[3];

    // JAX key schedule: key(42)=(0,42); fold-like split: keys[i]=threefry(k,(0,i))
    GibbsKeys keys;
    uint32_t k0 = 0u, k1 = 42u;
    for (int t = 0; t < KSTEPS; t++) {
        uint32_t n0, n1, h0, h1, w0, w1;
        tf2x32_host(k0, k1, 0u, 0u, &n0, &n1);
        tf2x32_host(k0, k1, 0u, 1u, &h0, &h1);
        tf2x32_host(k0, k1, 0u, 2u, &w0, &w1);
        uint32_t hs = h0 ^ h1 ^ 0x1BD11BDAu;
        uint32_t ws = w0 ^ w1 ^ 0x1BD11BDAu;
        keys.kh[t] = TFKey{h0, h1, hs, hs + 1u, h0 + 2u, h1 + 3u, hs + 4u, h0 + 5u};
        keys.kv[t] = TFKey{w0, w1, ws, ws + 1u, w0 + 2u, w1 + 3u, ws + 4u, w0 + 5u};
        k0 = n0; k1 = n1;
    }

    cudaFuncSetAttribute(rbm_kernel, cudaFuncAttributeMaxDynamicSharedMemorySize, SMEM_BYTES);
    rbm_kernel<<<PGRID, TPB, SMEM_BYTES>>>(v_data, kern, bsc, cvec, keys, 1u);
    reduce_kernel<<<1, 1024>>>((float*)d_out);
}